// round 12
// baseline (speedup 1.0000x reference)
#include <cuda_runtime.h>
#include <cstdint>

// Problem constants: B=2, S=2048, D=1024, H=16, DK=64
#define Bb  2
#define Ss  2048
#define Dd  1024
#define Hh  16
#define DKk 64

// Scratch (device globals; allocation-free).
__device__ float g_q[(size_t)Bb * Hh * Ss * DKk];
__device__ float g_k[(size_t)Bb * Hh * Ss * DKk];   // dk-pair-permuted layout
__device__ float g_v[(size_t)Bb * Hh * Ss * DKk];
__device__ float g_o[(size_t)Bb * Ss * Dd];
// tf32-pre-rounded copies of inputs and weights
__device__ float g_rq[(size_t)Bb * Ss * Dd];
__device__ float g_rk[(size_t)Bb * Ss * Dd];
__device__ float g_rv[(size_t)Bb * Ss * Dd];
__device__ float g_rwq[(size_t)Dd * Dd];
__device__ float g_rwk[(size_t)Dd * Dd];
__device__ float g_rwv[(size_t)Dd * Dd];
__device__ float g_rwo[(size_t)Dd * Dd];

// ---------------------------------------------------------------------------
// helpers
// ---------------------------------------------------------------------------
__device__ __forceinline__ uint32_t f2tf32(float f) {
    uint32_t r;
    asm("cvt.rna.tf32.f32 %0, %1;" : "=r"(r) : "f"(f));
    return r;
}
__device__ __forceinline__ float rndtf(float f) { return __uint_as_float(f2tf32(f)); }

__device__ __forceinline__ void mma_tf32(float d[4],
                                         uint32_t a0, uint32_t a1, uint32_t a2, uint32_t a3,
                                         uint32_t b0, uint32_t b1) {
    asm volatile(
        "mma.sync.aligned.m16n8k8.row.col.f32.tf32.tf32.f32 "
        "{%0,%1,%2,%3},{%4,%5,%6,%7},{%8,%9},{%0,%1,%2,%3};"
        : "+f"(d[0]), "+f"(d[1]), "+f"(d[2]), "+f"(d[3])
        : "r"(a0), "r"(a1), "r"(a2), "r"(a3), "r"(b0), "r"(b1));
}

#define CP_ASYNC16(dst_u32, src) \
    asm volatile("cp.async.cg.shared.global [%0], [%1], 16;" :: "r"(dst_u32), "l"(src))
#define CP_COMMIT() asm volatile("cp.async.commit_group;")
#define CP_WAIT(n)  asm volatile("cp.async.wait_group %0;" :: "n"(n))

// ---------------------------------------------------------------------------
// Pre-round kernels: copy with cvt.rna.tf32 (vectorized).
// ---------------------------------------------------------------------------
__device__ __forceinline__ float4 rnd4(float4 v) {
    v.x = rndtf(v.x); v.y = rndtf(v.y); v.z = rndtf(v.z); v.w = rndtf(v.w);
    return v;
}

__global__ void __launch_bounds__(256)
preround_inp(const float* __restrict__ q, const float* __restrict__ k,
             const float* __restrict__ v)
{
    const int z = blockIdx.z;
    const float4* src = (const float4*)((z == 0) ? q : (z == 1) ? k : v);
    float4* dst = (float4*)((z == 0) ? g_rq : (z == 1) ? g_rk : g_rv);
    const int i = blockIdx.x * blockDim.x + threadIdx.x;
    dst[i] = rnd4(src[i]);
}

__global__ void __launch_bounds__(256)
preround_w(const float* __restrict__ wq, const float* __restrict__ wk,
           const float* __restrict__ wv, const float* __restrict__ wo)
{
    const int z = blockIdx.z;
    const float4* src = (const float4*)((z == 0) ? wq : (z == 1) ? wk : (z == 2) ? wv : wo);
    float4* dst = (float4*)((z == 0) ? g_rwq : (z == 1) ? g_rwk : (z == 2) ? g_rwv : g_rwo);
    const int i = blockIdx.x * blockDim.x + threadIdx.x;
    dst[i] = rnd4(src[i]);
}

// ---------------------------------------------------------------------------
// tf32 GEMM with cp.async 3-stage pipeline (R7-passing structure).
// MODE 0: row-major to dst. MODE 1: head-split [B,H,S,DK], tf32-rounded.
// permk (runtime): permute dk within 8-blocks so (c, c+4) pairs are adjacent
// (enables LDS.64 K-fragment loads in attention). Runtime -> ONE template
// instantiation per kernel -> 48 KB static smem.
// ---------------------------------------------------------------------------
template <int MODE>
__device__ __forceinline__ void gemm_body(const float* __restrict__ A,
                                          const float* __restrict__ W,
                                          const float* __restrict__ bias,
                                          float* __restrict__ dst, int permk)
{
    const int K = Dd, N = Dd;
    __shared__ float sA[3][128 * 16];
    __shared__ float sW[3][128 * 16];

    const int tid  = threadIdx.x;
    const int m0   = blockIdx.y << 7;
    const int n0   = blockIdx.x << 7;
    const int warp = tid >> 5;
    const int lane = tid & 31;
    const int g    = lane >> 2;
    const int c    = lane & 3;
    const int wm   = (warp >> 1) << 6;
    const int wn   = (warp & 1) << 6;
    const int key  = (g >> 1) & 3;

    const int r0 = tid >> 2;
    const int q  = tid & 3;
    const int dst0 = r0 * 16 + ((q ^ ((r0 >> 1) & 3)) << 2);

    float acc[4][8][4];
#pragma unroll
    for (int mi = 0; mi < 4; ++mi)
#pragma unroll
        for (int ni = 0; ni < 8; ++ni)
#pragma unroll
            for (int e = 0; e < 4; ++e) acc[mi][ni][e] = 0.f;

    const float* Ap = A + (size_t)(m0 + r0) * K + (q << 2);
    const float* Wp = W + (size_t)(n0 + r0) * K + (q << 2);

    auto prefetch = [&](int st, int k0) {
        uint32_t da = (uint32_t)__cvta_generic_to_shared(&sA[st][dst0]);
        uint32_t dw = (uint32_t)__cvta_generic_to_shared(&sW[st][dst0]);
        const float* pa = Ap + k0;
        const float* pw = Wp + k0;
#pragma unroll
        for (int i = 0; i < 4; ++i) {
            CP_ASYNC16(da + i * 2048, pa + (size_t)(i << 5) * K);
            CP_ASYNC16(dw + i * 2048, pw + (size_t)(i << 5) * K);
        }
        CP_COMMIT();
    };

    auto compute = [&](const float* Ab, const float* Wb) {
#pragma unroll
        for (int s = 0; s < 2; ++s) {
            const int col0 = ((s << 3) + c) ^ (key << 2);
            const int col1 = ((s << 3) + c + 4) ^ (key << 2);
            uint32_t b0[8], b1[8];
#pragma unroll
            for (int ni = 0; ni < 8; ++ni) {
                const int r = (wn + (ni << 3) + g) << 4;
                b0[ni] = __float_as_uint(Wb[r + col0]);
                b1[ni] = __float_as_uint(Wb[r + col1]);
            }
#pragma unroll
            for (int mi = 0; mi < 4; ++mi) {
                const int ra = (wm + (mi << 4) + g) << 4;
                const int rb = ra + (8 << 4);
                const uint32_t a0 = __float_as_uint(Ab[ra + col0]);
                const uint32_t a1 = __float_as_uint(Ab[rb + col0]);
                const uint32_t a2 = __float_as_uint(Ab[ra + col1]);
                const uint32_t a3 = __float_as_uint(Ab[rb + col1]);
#pragma unroll
                for (int ni = 0; ni < 8; ++ni)
                    mma_tf32(acc[mi][ni], a0, a1, a2, a3, b0[ni], b1[ni]);
            }
        }
    };

    const int KT = K / 16;
    prefetch(0, 0);
    prefetch(1, 16);

    for (int kt = 0; kt < KT; ++kt) {
        if (kt < KT - 2) { CP_WAIT(1); } else { CP_WAIT(0); }
        __syncthreads();
        if (kt + 2 < KT) prefetch((kt + 2) % 3, (kt + 2) << 4);
        const int st = kt % 3;
        compute(sA[st], sW[st]);
        __syncthreads();
    }

#pragma unroll
    for (int mi = 0; mi < 4; ++mi) {
        const int m_lo = m0 + wm + (mi << 4) + g;
#pragma unroll
        for (int ni = 0; ni < 8; ++ni) {
            const int n_b = n0 + wn + (ni << 3) + (c << 1);
#pragma unroll
            for (int e = 0; e < 4; ++e) {
                const int m = m_lo + ((e >> 1) << 3);
                const int n = n_b + (e & 1);
                float v = acc[mi][ni][e] + bias[n];
                if (MODE == 0) {
                    dst[(size_t)m * N + n] = v;
                } else {
                    v = rndtf(v);
                    const int b = m >> 11, s2 = m & (Ss - 1);
                    const int h = n >> 6;
                    int dk = n & 63;
                    if (permk) {
                        const int kl = dk & 7;
                        dk = (dk & ~7) | ((kl & 3) << 1) | ((kl >> 2) & 1);
                    }
                    dst[(((size_t)(b * Hh + h)) * Ss + s2) * DKk + dk] = v;
                }
            }
        }
    }
}

__global__ void __launch_bounds__(128)
qkv_gemm(const float* __restrict__ bq, const float* __restrict__ bk,
         const float* __restrict__ bv)
{
    const int z = blockIdx.z;
    const float* A  = (z == 0) ? g_rq  : (z == 1) ? g_rk  : g_rv;
    const float* W  = (z == 0) ? g_rwq : (z == 1) ? g_rwk : g_rwv;
    const float* bi = (z == 0) ? bq : (z == 1) ? bk : bv;
    float* dst      = (z == 0) ? g_q : (z == 1) ? g_k : g_v;
    gemm_body<1>(A, W, bi, dst, z == 1);
}

__global__ void __launch_bounds__(128)
out_gemm(const float* __restrict__ bias, float* __restrict__ Cout)
{
    gemm_body<0>(g_o, g_rwo, bias, Cout, 0);
}

// ---------------------------------------------------------------------------
// Causal flash attention, tf32 mma.sync.
// CTA: 128 q-rows, 256 threads = 8 warps x 16 rows. KV-tile 32 rows,
// 3-stage cp.async pipeline (48 KB static), ONE __syncthreads per tile.
// Q in registers. K smem: pair-permuted rows (via g_k layout) with slab-XOR
// swizzle -> LDS.64 fragment loads. QK^T B-rows permuted by pg so the
// S accumulator IS the PV A-fragment (no shuffles). V: f4-block swizzle.
// ---------------------------------------------------------------------------
__global__ void __launch_bounds__(256, 2)
flash_attn_mma()
{
    __shared__ float sK[3][32 * 64];
    __shared__ float sV[3][32 * 64];   // total 48 KB exactly

    const int qt  = (gridDim.x - 1) - blockIdx.x;  // heavy tiles first
    const int bh  = blockIdx.y;
    const int tid = threadIdx.x;
    const int warp = tid >> 5;
    const int lane = tid & 31;
    const int g    = lane >> 2;   // 0..7
    const int c    = lane & 3;    // 0..3
    const int wrow = warp << 4;   // 0..112
    const int qbase = qt << 7;
    const int pg   = (g >> 1) | ((g & 1) << 2);  // B-row permutation

    // staging map: thread -> row sr (0..31), chunk sc8 (0..7; also +8)
    const int sr  = tid >> 3;
    const int sc8 = tid & 7;

    const float* Qb = g_q + (size_t)bh * Ss * DKk;
    const float* Kb = g_k + (size_t)bh * Ss * DKk;
    const float* Vb = g_v + (size_t)bh * Ss * DKk;

    // ---- Q fragments in registers (rows wrow+g, wrow+g+8; all 64 cols) ----
    uint32_t qa0[8], qa1[8], qa2[8], qa3[8];
    {
        const float* Q0 = Qb + (size_t)(qbase + wrow + g) * DKk;
        const float* Q1 = Q0 + (size_t)8 * DKk;
#pragma unroll
        for (int s = 0; s < 8; ++s) {
            qa0[s] = __float_as_uint(Q0[(s << 3) + c]);
            qa1[s] = __float_as_uint(Q1[(s << 3) + c]);
            qa2[s] = __float_as_uint(Q0[(s << 3) + c + 4]);
            qa3[s] = __float_as_uint(Q1[(s << 3) + c + 4]);
        }
    }

    float m0 = -1e30f, m1 = -1e30f, l0 = 0.f, l1 = 0.f;
    float o[8][4];
#pragma unroll
    for (int nt = 0; nt < 8; ++nt)
#pragma unroll
        for (int e = 0; e < 4; ++e) o[nt][e] = 0.f;

    const float scale = 0.125f;  // 1/sqrt(64)
    const int T = (qt << 2) + 4;     // kv tiles of 32 rows
    const int firstDiag = qt << 2;   // tiles >= this need masking

    // K dest: chunk ch (0..15): slab = ch>>1, half = ch&1.
    //   word = sr*64 + ((slab ^ (sr&7))<<3) + (half<<2)
    // V dest: word = sr*64 + ((ch ^ (sr&3))<<2)
#define PREFETCH_KV(st, kt)                                                    \
    {                                                                          \
        const int kb_ = (kt) << 5;                                             \
        const float* ksrc = Kb + (size_t)(kb_ + sr) * DKk;                     \
        const float* vsrc = Vb + (size_t)(kb_ + sr) * DKk;                     \
        const int kkey = sr & 7;                                               \
        const int vkey = sr & 3;                                               \
        const int ch0 = sc8, ch1 = sc8 + 8;                                    \
        uint32_t kd0 = (uint32_t)__cvta_generic_to_shared(                     \
            &sK[st][(sr << 6) + (((ch0 >> 1) ^ kkey) << 3) + ((ch0 & 1) << 2)]); \
        uint32_t kd1 = (uint32_t)__cvta_generic_to_shared(                     \
            &sK[st][(sr << 6) + (((ch1 >> 1) ^ kkey) << 3) + ((ch1 & 1) << 2)]); \
        uint32_t vd0 = (uint32_t)__cvta_generic_to_shared(                     \
            &sV[st][(sr << 6) + ((ch0 ^ vkey) << 2)]);                         \
        uint32_t vd1 = (uint32_t)__cvta_generic_to_shared(                     \
            &sV[st][(sr << 6) + ((ch1 ^ vkey) << 2)]);                         \
        CP_ASYNC16(kd0, ksrc + (ch0 << 2));                                    \
        CP_ASYNC16(kd1, ksrc + (ch1 << 2));                                    \
        CP_ASYNC16(vd0, vsrc + (ch0 << 2));                                    \
        CP_ASYNC16(vd1, vsrc + (ch1 << 2));                                    \
        CP_COMMIT();                                                           \
    }

    PREFETCH_KV(0, 0);
    PREFETCH_KV(1, 1);

    for (int kt = 0; kt < T; ++kt) {
        if (kt < T - 1) { CP_WAIT(1); } else { CP_WAIT(0); }
        __syncthreads();   // tile kt ready; all warps done with stage (kt+2)%3
        if (kt + 2 < T) PREFETCH_KV((kt + 2) % 3, kt + 2);

        const float* Kt = sK[kt % 3];
        const float* Vt = sV[kt % 3];
        const int kbase = kt << 5;

        // ---- S = Q K^T (B-rows permuted by pg) ----
        float s[4][4];
#pragma unroll
        for (int nt = 0; nt < 4; ++nt)
#pragma unroll
            for (int e = 0; e < 4; ++e) s[nt][e] = 0.f;

#pragma unroll
        for (int sl = 0; sl < 8; ++sl) {
#pragma unroll
            for (int nt = 0; nt < 4; ++nt) {
                const int R = (nt << 3) + pg;
                const float2 kb = *(const float2*)&Kt[(R << 6) + ((sl ^ pg) << 3) + (c << 1)];
                mma_tf32(s[nt], qa0[sl], qa1[sl], qa2[sl], qa3[sl],
                         __float_as_uint(kb.x), __float_as_uint(kb.y));
            }
        }

        // ---- scale + causal mask (acc cols are keys c, c+4 of each nt) ----
        const int rl0 = qbase + wrow + g, rl1 = rl0 + 8;
        if (kt >= firstDiag) {
#pragma unroll
            for (int nt = 0; nt < 4; ++nt) {
                const int cl = kbase + (nt << 3) + c;
                s[nt][0] = (cl     > rl0) ? -1e30f : s[nt][0] * scale;
                s[nt][1] = (cl + 4 > rl0) ? -1e30f : s[nt][1] * scale;
                s[nt][2] = (cl     > rl1) ? -1e30f : s[nt][2] * scale;
                s[nt][3] = (cl + 4 > rl1) ? -1e30f : s[nt][3] * scale;
            }
        } else {
#pragma unroll
            for (int nt = 0; nt < 4; ++nt) {
                s[nt][0] *= scale; s[nt][1] *= scale;
                s[nt][2] *= scale; s[nt][3] *= scale;
            }
        }

        // ---- online softmax (rows rl0: e0/e1; rl1: e2/e3) ----
        float mx0 = -1e30f, mx1 = -1e30f;
#pragma unroll
        for (int nt = 0; nt < 4; ++nt) {
            mx0 = fmaxf(mx0, fmaxf(s[nt][0], s[nt][1]));
            mx1 = fmaxf(mx1, fmaxf(s[nt][2], s[nt][3]));
        }
        mx0 = fmaxf(mx0, __shfl_xor_sync(0xffffffffu, mx0, 1));
        mx0 = fmaxf(mx0, __shfl_xor_sync(0xffffffffu, mx0, 2));
        mx1 = fmaxf(mx1, __shfl_xor_sync(0xffffffffu, mx1, 1));
        mx1 = fmaxf(mx1, __shfl_xor_sync(0xffffffffu, mx1, 2));

        const float mn0 = fmaxf(m0, mx0);
        const float mn1 = fmaxf(m1, mx1);
        const float fac0 = __expf(m0 - mn0);
        const float fac1 = __expf(m1 - mn1);
        m0 = mn0; m1 = mn1;

        float sum0 = 0.f, sum1 = 0.f;
#pragma unroll
        for (int nt = 0; nt < 4; ++nt) {
            s[nt][0] = __expf(s[nt][0] - mn0); sum0 += s[nt][0];
            s[nt][1] = __expf(s[nt][1] - mn0); sum0 += s[nt][1];
            s[nt][2] = __expf(s[nt][2] - mn1); sum1 += s[nt][2];
            s[nt][3] = __expf(s[nt][3] - mn1); sum1 += s[nt][3];
        }
        sum0 += __shfl_xor_sync(0xffffffffu, sum0, 1);
        sum0 += __shfl_xor_sync(0xffffffffu, sum0, 2);
        sum1 += __shfl_xor_sync(0xffffffffu, sum1, 1);
        sum1 += __shfl_xor_sync(0xffffffffu, sum1, 2);
        l0 = l0 * fac0 + sum0;
        l1 = l1 * fac1 + sum1;

#pragma unroll
        for (int nt = 0; nt < 4; ++nt) {
            s[nt][0] = rndtf(s[nt][0]);
            s[nt][1] = rndtf(s[nt][1]);
            s[nt][2] = rndtf(s[nt][2]);
            s[nt][3] = rndtf(s[nt][3]);
        }
#pragma unroll
        for (int nt = 0; nt < 8; ++nt) {
            o[nt][0] *= fac0; o[nt][1] *= fac0;
            o[nt][2] *= fac1; o[nt][3] *= fac1;
        }

        // ---- O += P V : S acc IS the A-fragment (a = s[ks][{0,2,1,3}]) ----
#pragma unroll
        for (int ks = 0; ks < 4; ++ks) {
            const uint32_t a0 = __float_as_uint(s[ks][0]);
            const uint32_t a1 = __float_as_uint(s[ks][2]);
            const uint32_t a2 = __float_as_uint(s[ks][1]);
            const uint32_t a3 = __float_as_uint(s[ks][3]);
            const int kr0 = (ks << 3) + c;
            const int kr1 = kr0 + 4;
#pragma unroll
            for (int nt = 0; nt < 8; ++nt) {
                const int col = (nt << 3) + g;
                const float vb0 = Vt[(kr0 << 6) + ((((col >> 2) ^ (kr0 & 3)) << 2) | (col & 3))];
                const float vb1 = Vt[(kr1 << 6) + ((((col >> 2) ^ (kr1 & 3)) << 2) | (col & 3))];
                mma_tf32(o[nt], a0, a1, a2, a3,
                         __float_as_uint(vb0), __float_as_uint(vb1));
            }
        }
    }

    // ---- epilogue: normalize, tf32-round, write g_o [B,S,D] ----
    const int b = bh >> 4, h = bh & 15;
    const float inv0 = 1.f / l0, inv1 = 1.f / l1;
    const int row0 = qbase + wrow + g;
    const int row1 = row0 + 8;
    float* O0 = g_o + ((size_t)(b * Ss + row0)) * Dd + (h << 6);
    float* O1 = g_o + ((size_t)(b * Ss + row1)) * Dd + (h << 6);
#pragma unroll
    for (int nt = 0; nt < 8; ++nt) {
        const int cl = (nt << 3) + (c << 1);
        O0[cl]     = rndtf(o[nt][0] * inv0);
        O0[cl + 1] = rndtf(o[nt][1] * inv0);
        O1[cl]     = rndtf(o[nt][2] * inv1);
        O1[cl + 1] = rndtf(o[nt][3] * inv1);
    }
#undef PREFETCH_KV
}

// ---------------------------------------------------------------------------
// Launch. Inputs: 0 query, 1 key, 2 value, 3 mask (tril; hardcoded),
// 4..11: wq_w, wq_b, wk_w, wk_b, wv_w, wv_b, wo_w, wo_b.
// ---------------------------------------------------------------------------
extern "C" void kernel_launch(void* const* d_in, const int* in_sizes, int n_in,
                              void* d_out, int out_size)
{
    const float* query = (const float*)d_in[0];
    const float* key   = (const float*)d_in[1];
    const float* value = (const float*)d_in[2];
    const float* wq_w  = (const float*)d_in[4];
    const float* wq_b  = (const float*)d_in[5];
    const float* wk_w  = (const float*)d_in[6];
    const float* wk_b  = (const float*)d_in[7];
    const float* wv_w  = (const float*)d_in[8];
    const float* wv_b  = (const float*)d_in[9];
    const float* wo_w  = (const float*)d_in[10];
    const float* wo_b  = (const float*)d_in[11];
    float* out = (float*)d_out;

    const dim3 pi_grid((Bb * Ss * Dd) / 4 / 256, 1, 3);
    const dim3 pw_grid((Dd * Dd) / 4 / 256, 1, 4);
    const dim3 qkv_grid(Dd / 128, (Bb * Ss) / 128, 3);
    const dim3 gemm_grid(Dd / 128, (Bb * Ss) / 128);
    const dim3 attn_grid(Ss / 128, Bb * Hh);  // (16, 32)

    preround_inp<<<pi_grid, 256>>>(query, key, value);
    preround_w<<<pw_grid, 256>>>(wq_w, wk_w, wv_w, wo_w);
    qkv_gemm<<<qkv_grid, 128>>>(wq_b, wk_b, wv_b);
    flash_attn_mma<<<attn_grid, 256>>>();
    out_gemm<<<gemm_grid, 128>>>(wo_b, out);
}

// round 15
// speedup vs baseline: 1.2127x; 1.2127x over previous
#include <cuda_runtime.h>
#include <cstdint>

// Problem constants: B=2, S=2048, D=1024, H=16, DK=64
#define Bb  2
#define Ss  2048
#define Dd  1024
#define Hh  16
#define DKk 64

// Scratch (device globals; allocation-free).
__device__ float g_q[(size_t)Bb * Hh * Ss * DKk];
__device__ float g_k[(size_t)Bb * Hh * Ss * DKk];   // [B,H,S,DK], dk pair-permuted
__device__ float g_v[(size_t)Bb * Hh * Ss * DKk];   // [B,H,DK,S] TRANSPOSED, s pair-permuted
__device__ float g_o[(size_t)Bb * Ss * Dd];
// tf32-pre-rounded copies of inputs and weights
__device__ float g_rq[(size_t)Bb * Ss * Dd];
__device__ float g_rk[(size_t)Bb * Ss * Dd];
__device__ float g_rv[(size_t)Bb * Ss * Dd];
__device__ float g_rwq[(size_t)Dd * Dd];
__device__ float g_rwk[(size_t)Dd * Dd];
__device__ float g_rwv[(size_t)Dd * Dd];
__device__ float g_rwo[(size_t)Dd * Dd];

// ---------------------------------------------------------------------------
// helpers
// ---------------------------------------------------------------------------
__device__ __forceinline__ uint32_t f2tf32(float f) {
    uint32_t r;
    asm("cvt.rna.tf32.f32 %0, %1;" : "=r"(r) : "f"(f));
    return r;
}
__device__ __forceinline__ float rndtf(float f) { return __uint_as_float(f2tf32(f)); }

__device__ __forceinline__ void mma_tf32(float d[4],
                                         uint32_t a0, uint32_t a1, uint32_t a2, uint32_t a3,
                                         uint32_t b0, uint32_t b1) {
    asm volatile(
        "mma.sync.aligned.m16n8k8.row.col.f32.tf32.tf32.f32 "
        "{%0,%1,%2,%3},{%4,%5,%6,%7},{%8,%9},{%0,%1,%2,%3};"
        : "+f"(d[0]), "+f"(d[1]), "+f"(d[2]), "+f"(d[3])
        : "r"(a0), "r"(a1), "r"(a2), "r"(a3), "r"(b0), "r"(b1));
}

#define CP_ASYNC16(dst_u32, src) \
    asm volatile("cp.async.cg.shared.global [%0], [%1], 16;" :: "r"(dst_u32), "l"(src))
#define CP_COMMIT() asm volatile("cp.async.commit_group;")
#define CP_WAIT(n)  asm volatile("cp.async.wait_group %0;" :: "n"(n))

// ---------------------------------------------------------------------------
// Pre-round kernels: copy with cvt.rna.tf32 (vectorized).
// ---------------------------------------------------------------------------
__device__ __forceinline__ float4 rnd4(float4 v) {
    v.x = rndtf(v.x); v.y = rndtf(v.y); v.z = rndtf(v.z); v.w = rndtf(v.w);
    return v;
}

__global__ void __launch_bounds__(256)
preround_inp(const float* __restrict__ q, const float* __restrict__ k,
             const float* __restrict__ v)
{
    const int z = blockIdx.z;
    const float4* src = (const float4*)((z == 0) ? q : (z == 1) ? k : v);
    float4* dst = (float4*)((z == 0) ? g_rq : (z == 1) ? g_rk : g_rv);
    const int i = blockIdx.x * blockDim.x + threadIdx.x;
    dst[i] = rnd4(src[i]);
}

__global__ void __launch_bounds__(256)
preround_w(const float* __restrict__ wq, const float* __restrict__ wk,
           const float* __restrict__ wv, const float* __restrict__ wo)
{
    const int z = blockIdx.z;
    const float4* src = (const float4*)((z == 0) ? wq : (z == 1) ? wk : (z == 2) ? wv : wo);
    float4* dst = (float4*)((z == 0) ? g_rwq : (z == 1) ? g_rwk : (z == 2) ? g_rwv : g_rwo);
    const int i = blockIdx.x * blockDim.x + threadIdx.x;
    dst[i] = rnd4(src[i]);
}

// ---------------------------------------------------------------------------
// tf32 GEMM with cp.async 3-stage pipeline.
// MODE 0: row-major to dst.
// MODE 1: head-split, tf32-rounded; vmode 0 = natural [B,H,S,DK] (Q),
//         vmode 1 = dk pair-permuted [B,H,S,DK] (K),
//         vmode 2 = transposed [B,H,DK,S] with s pair-permuted (V).
// Runtime vmode -> ONE instantiation per kernel -> 48 KB static smem.
// ---------------------------------------------------------------------------
template <int MODE>
__device__ __forceinline__ void gemm_body(const float* __restrict__ A,
                                          const float* __restrict__ W,
                                          const float* __restrict__ bias,
                                          float* __restrict__ dst, int vmode)
{
    const int K = Dd, N = Dd;
    __shared__ float sA[3][128 * 16];
    __shared__ float sW[3][128 * 16];

    const int tid  = threadIdx.x;
    const int m0   = blockIdx.y << 7;
    const int n0   = blockIdx.x << 7;
    const int warp = tid >> 5;
    const int lane = tid & 31;
    const int g    = lane >> 2;
    const int c    = lane & 3;
    const int wm   = (warp >> 1) << 6;
    const int wn   = (warp & 1) << 6;
    const int key  = (g >> 1) & 3;

    const int r0 = tid >> 2;
    const int q  = tid & 3;
    const int dst0 = r0 * 16 + ((q ^ ((r0 >> 1) & 3)) << 2);

    float acc[4][8][4];
#pragma unroll
    for (int mi = 0; mi < 4; ++mi)
#pragma unroll
        for (int ni = 0; ni < 8; ++ni)
#pragma unroll
            for (int e = 0; e < 4; ++e) acc[mi][ni][e] = 0.f;

    const float* Ap = A + (size_t)(m0 + r0) * K + (q << 2);
    const float* Wp = W + (size_t)(n0 + r0) * K + (q << 2);

    auto prefetch = [&](int st, int k0) {
        uint32_t da = (uint32_t)__cvta_generic_to_shared(&sA[st][dst0]);
        uint32_t dw = (uint32_t)__cvta_generic_to_shared(&sW[st][dst0]);
        const float* pa = Ap + k0;
        const float* pw = Wp + k0;
#pragma unroll
        for (int i = 0; i < 4; ++i) {
            CP_ASYNC16(da + i * 2048, pa + (size_t)(i << 5) * K);
            CP_ASYNC16(dw + i * 2048, pw + (size_t)(i << 5) * K);
        }
        CP_COMMIT();
    };

    auto compute = [&](const float* Ab, const float* Wb) {
#pragma unroll
        for (int s = 0; s < 2; ++s) {
            const int col0 = ((s << 3) + c) ^ (key << 2);
            const int col1 = ((s << 3) + c + 4) ^ (key << 2);
            uint32_t b0[8], b1[8];
#pragma unroll
            for (int ni = 0; ni < 8; ++ni) {
                const int r = (wn + (ni << 3) + g) << 4;
                b0[ni] = __float_as_uint(Wb[r + col0]);
                b1[ni] = __float_as_uint(Wb[r + col1]);
            }
#pragma unroll
            for (int mi = 0; mi < 4; ++mi) {
                const int ra = (wm + (mi << 4) + g) << 4;
                const int rb = ra + (8 << 4);
                const uint32_t a0 = __float_as_uint(Ab[ra + col0]);
                const uint32_t a1 = __float_as_uint(Ab[rb + col0]);
                const uint32_t a2 = __float_as_uint(Ab[ra + col1]);
                const uint32_t a3 = __float_as_uint(Ab[rb + col1]);
#pragma unroll
                for (int ni = 0; ni < 8; ++ni)
                    mma_tf32(acc[mi][ni], a0, a1, a2, a3, b0[ni], b1[ni]);
            }
        }
    };

    const int KT = K / 16;
    prefetch(0, 0);
    prefetch(1, 16);

    for (int kt = 0; kt < KT; ++kt) {
        if (kt < KT - 2) { CP_WAIT(1); } else { CP_WAIT(0); }
        __syncthreads();
        if (kt + 2 < KT) prefetch((kt + 2) % 3, (kt + 2) << 4);
        const int st = kt % 3;
        compute(sA[st], sW[st]);
        __syncthreads();
    }

#pragma unroll
    for (int mi = 0; mi < 4; ++mi) {
        const int m_lo = m0 + wm + (mi << 4) + g;
#pragma unroll
        for (int ni = 0; ni < 8; ++ni) {
            const int n_b = n0 + wn + (ni << 3) + (c << 1);
#pragma unroll
            for (int e = 0; e < 4; ++e) {
                const int m = m_lo + ((e >> 1) << 3);
                const int n = n_b + (e & 1);
                float v = acc[mi][ni][e] + bias[n];
                if (MODE == 0) {
                    dst[(size_t)m * N + n] = v;
                } else {
                    v = rndtf(v);
                    const int b = m >> 11, s2 = m & (Ss - 1);
                    const int h = n >> 6;
                    const int dk = n & 63;
                    if (vmode == 2) {
                        // V: transposed [B,H,DK,S], s pair-permuted within 8
                        const int sp = (s2 & ~7) | ((s2 & 3) << 1) | ((s2 >> 2) & 1);
                        dst[(((size_t)(b * Hh + h)) * DKk + dk) * Ss + sp] = v;
                    } else {
                        int dkw = dk;
                        if (vmode == 1) {
                            const int kl = dk & 7;
                            dkw = (dk & ~7) | ((kl & 3) << 1) | ((kl >> 2) & 1);
                        }
                        dst[(((size_t)(b * Hh + h)) * Ss + s2) * DKk + dkw] = v;
                    }
                }
            }
        }
    }
}

__global__ void __launch_bounds__(128)
qkv_gemm(const float* __restrict__ bq, const float* __restrict__ bk,
         const float* __restrict__ bv)
{
    const int z = blockIdx.z;
    const float* A  = (z == 0) ? g_rq  : (z == 1) ? g_rk  : g_rv;
    const float* W  = (z == 0) ? g_rwq : (z == 1) ? g_rwk : g_rwv;
    const float* bi = (z == 0) ? bq : (z == 1) ? bk : bv;
    float* dst      = (z == 0) ? g_q : (z == 1) ? g_k : g_v;
    gemm_body<1>(A, W, bi, dst, z);
}

__global__ void __launch_bounds__(128)
out_gemm(const float* __restrict__ bias, float* __restrict__ Cout)
{
    gemm_body<0>(g_o, g_rwo, bias, Cout, 0);
}

// ---------------------------------------------------------------------------
// Causal flash attention, tf32 mma.sync.
// CTA: 128 q-rows, 256 threads = 8 warps x 16 rows. KV-tile 32 rows,
// 3-stage cp.async pipeline (48 KB), ONE __syncthreads per tile.
// Q in registers. K smem [32 kv x 64 dk]: word = r*64 + ((p>>2 ^ Hk(r))<<2)
// + (p&3), Hk(r) = ((r&1)<<2)|(((r>>2)&1)<<1) -> conflict-free LDS.64 frags.
// V smem is V^T [64 dk x 32 kv]: word = r*32 + ((p>>2 ^ Hv(r))<<2) + (p&3),
// Hv(r) = (r&3)<<1 -> conflict-free LDS.64 B-frags (halves V instructions).
// QK^T B-rows permuted by pg so S accumulator IS the PV A-fragment.
// ---------------------------------------------------------------------------
__global__ void __launch_bounds__(256, 2)
flash_attn_mma()
{
    __shared__ float sK[3][32 * 64];
    __shared__ float sV[3][64 * 32];   // V^T tiles; total 48 KB exactly

    const int qt  = (gridDim.x - 1) - blockIdx.x;  // heavy tiles first
    const int bh  = blockIdx.y;
    const int tid = threadIdx.x;
    const int warp = tid >> 5;
    const int lane = tid & 31;
    const int g    = lane >> 2;   // 0..7
    const int c    = lane & 3;    // 0..3
    const int wrow = warp << 4;   // 0..112
    const int qbase = qt << 7;
    const int pg   = (g >> 1) | ((g & 1) << 2);  // B-row permutation
    const int hkt  = ((pg & 1) << 2) | (((pg >> 2) & 1) << 1);  // Hk of row nt*8+pg
    const int hvt  = (g & 3) << 1;                              // Hv of row nt*8+g

    // staging maps
    const int sr  = tid >> 3;          // K: kv row 0..31
    const int sc8 = tid & 7;           // K: chunk 0..7 (+8)
    const int vr  = tid >> 2;          // V^T: dk row 0..63
    const int vc2 = (tid & 3) << 1;    // V^T: chunks vc2, vc2+1

    const float* Qb = g_q + (size_t)bh * Ss * DKk;
    const float* Kb = g_k + (size_t)bh * Ss * DKk;
    const float* Vb = g_v + (size_t)bh * DKk * Ss;  // transposed block

    // ---- Q fragments in registers (rows wrow+g, wrow+g+8; all 64 cols) ----
    uint32_t qa0[8], qa1[8], qa2[8], qa3[8];
    {
        const float* Q0 = Qb + (size_t)(qbase + wrow + g) * DKk;
        const float* Q1 = Q0 + (size_t)8 * DKk;
#pragma unroll
        for (int s = 0; s < 8; ++s) {
            qa0[s] = __float_as_uint(Q0[(s << 3) + c]);
            qa1[s] = __float_as_uint(Q1[(s << 3) + c]);
            qa2[s] = __float_as_uint(Q0[(s << 3) + c + 4]);
            qa3[s] = __float_as_uint(Q1[(s << 3) + c + 4]);
        }
    }

    float m0 = -1e30f, m1 = -1e30f, l0 = 0.f, l1 = 0.f;
    float o[8][4];
#pragma unroll
    for (int nt = 0; nt < 8; ++nt)
#pragma unroll
        for (int e = 0; e < 4; ++e) o[nt][e] = 0.f;

    const float scale = 0.125f;  // 1/sqrt(64)
    const int T = (qt << 2) + 4;     // kv tiles of 32 rows
    const int firstDiag = qt << 2;   // tiles >= this need masking

#define PREFETCH_KV(st, kt)                                                    \
    {                                                                          \
        const int kb_ = (kt) << 5;                                             \
        const float* ksrc = Kb + (size_t)(kb_ + sr) * DKk;                     \
        const float* vsrc = Vb + (size_t)vr * Ss + kb_;                        \
        const int hk_ = ((sr & 1) << 2) | (((sr >> 2) & 1) << 1);              \
        const int hv_ = (vr & 3) << 1;                                         \
        const int kch0 = sc8, kch1 = sc8 + 8;                                  \
        uint32_t kd0 = (uint32_t)__cvta_generic_to_shared(                     \
            &sK[st][(sr << 6) + ((kch0 ^ hk_) << 2)]);                         \
        uint32_t kd1 = (uint32_t)__cvta_generic_to_shared(                     \
            &sK[st][(sr << 6) + ((kch1 ^ hk_) << 2)]);                         \
        uint32_t vd0 = (uint32_t)__cvta_generic_to_shared(                     \
            &sV[st][(vr << 5) + ((vc2 ^ hv_) << 2)]);                          \
        uint32_t vd1 = (uint32_t)__cvta_generic_to_shared(                     \
            &sV[st][(vr << 5) + (((vc2 + 1) ^ hv_) << 2)]);                    \
        CP_ASYNC16(kd0, ksrc + (kch0 << 2));                                   \
        CP_ASYNC16(kd1, ksrc + (kch1 << 2));                                   \
        CP_ASYNC16(vd0, vsrc + (vc2 << 2));                                    \
        CP_ASYNC16(vd1, vsrc + ((vc2 + 1) << 2));                              \
        CP_COMMIT();                                                           \
    }

    PREFETCH_KV(0, 0);
    PREFETCH_KV(1, 1);

    for (int kt = 0; kt < T; ++kt) {
        if (kt < T - 1) { CP_WAIT(1); } else { CP_WAIT(0); }
        __syncthreads();   // tile kt ready; all warps done with stage (kt+2)%3
        if (kt + 2 < T) PREFETCH_KV((kt + 2) % 3, kt + 2);

        const float* Kt = sK[kt % 3];
        const float* Vt = sV[kt % 3];
        const int kbase = kt << 5;

        // ---- S = Q K^T (B-rows permuted by pg; conflict-free LDS.64) ----
        float s[4][4];
#pragma unroll
        for (int nt = 0; nt < 4; ++nt)
#pragma unroll
            for (int e = 0; e < 4; ++e) s[nt][e] = 0.f;

#pragma unroll
        for (int sl = 0; sl < 8; ++sl) {
            const int coff = ((((sl << 1) + (c >> 1)) ^ hkt) << 2) + ((c & 1) << 1);
#pragma unroll
            for (int nt = 0; nt < 4; ++nt) {
                const int R = (nt << 3) + pg;
                const float2 kb = *(const float2*)&Kt[(R << 6) + coff];
                mma_tf32(s[nt], qa0[sl], qa1[sl], qa2[sl], qa3[sl],
                         __float_as_uint(kb.x), __float_as_uint(kb.y));
            }
        }

        // ---- scale + causal mask (acc cols are keys c, c+4 of each nt) ----
        const int rl0 = qbase + wrow + g, rl1 = rl0 + 8;
        if (kt >= firstDiag) {
#pragma unroll
            for (int nt = 0; nt < 4; ++nt) {
                const int cl = kbase + (nt << 3) + c;
                s[nt][0] = (cl     > rl0) ? -1e30f : s[nt][0] * scale;
                s[nt][1] = (cl + 4 > rl0) ? -1e30f : s[nt][1] * scale;
                s[nt][2] = (cl     > rl1) ? -1e30f : s[nt][2] * scale;
                s[nt][3] = (cl + 4 > rl1) ? -1e30f : s[nt][3] * scale;
            }
        } else {
#pragma unroll
            for (int nt = 0; nt < 4; ++nt) {
                s[nt][0] *= scale; s[nt][1] *= scale;
                s[nt][2] *= scale; s[nt][3] *= scale;
            }
        }

        // ---- online softmax (rows rl0: e0/e1; rl1: e2/e3) ----
        float mx0 = -1e30f, mx1 = -1e30f;
#pragma unroll
        for (int nt = 0; nt < 4; ++nt) {
            mx0 = fmaxf(mx0, fmaxf(s[nt][0], s[nt][1]));
            mx1 = fmaxf(mx1, fmaxf(s[nt][2], s[nt][3]));
        }
        mx0 = fmaxf(mx0, __shfl_xor_sync(0xffffffffu, mx0, 1));
        mx0 = fmaxf(mx0, __shfl_xor_sync(0xffffffffu, mx0, 2));
        mx1 = fmaxf(mx1, __shfl_xor_sync(0xffffffffu, mx1, 1));
        mx1 = fmaxf(mx1, __shfl_xor_sync(0xffffffffu, mx1, 2));

        const float mn0 = fmaxf(m0, mx0);
        const float mn1 = fmaxf(m1, mx1);
        const float fac0 = __expf(m0 - mn0);
        const float fac1 = __expf(m1 - mn1);
        m0 = mn0; m1 = mn1;

        float sum0 = 0.f, sum1 = 0.f;
#pragma unroll
        for (int nt = 0; nt < 4; ++nt) {
            s[nt][0] = __expf(s[nt][0] - mn0); sum0 += s[nt][0];
            s[nt][1] = __expf(s[nt][1] - mn0); sum0 += s[nt][1];
            s[nt][2] = __expf(s[nt][2] - mn1); sum1 += s[nt][2];
            s[nt][3] = __expf(s[nt][3] - mn1); sum1 += s[nt][3];
        }
        sum0 += __shfl_xor_sync(0xffffffffu, sum0, 1);
        sum0 += __shfl_xor_sync(0xffffffffu, sum0, 2);
        sum1 += __shfl_xor_sync(0xffffffffu, sum1, 1);
        sum1 += __shfl_xor_sync(0xffffffffu, sum1, 2);
        l0 = l0 * fac0 + sum0;
        l1 = l1 * fac1 + sum1;

#pragma unroll
        for (int nt = 0; nt < 4; ++nt) {
            s[nt][0] = rndtf(s[nt][0]);
            s[nt][1] = rndtf(s[nt][1]);
            s[nt][2] = rndtf(s[nt][2]);
            s[nt][3] = rndtf(s[nt][3]);
        }
#pragma unroll
        for (int nt = 0; nt < 8; ++nt) {
            o[nt][0] *= fac0; o[nt][1] *= fac0;
            o[nt][2] *= fac1; o[nt][3] *= fac1;
        }

        // ---- O += P V : S acc IS the A-fragment; V^T LDS.64 B-frags ----
#pragma unroll
        for (int ks = 0; ks < 4; ++ks) {
            const uint32_t a0 = __float_as_uint(s[ks][0]);
            const uint32_t a1 = __float_as_uint(s[ks][2]);
            const uint32_t a2 = __float_as_uint(s[ks][1]);
            const uint32_t a3 = __float_as_uint(s[ks][3]);
            const int voff = ((((ks << 1) + (c >> 1)) ^ hvt) << 2) + ((c & 1) << 1);
#pragma unroll
            for (int nt = 0; nt < 8; ++nt) {
                const int row = (nt << 3) + g;
                const float2 vb = *(const float2*)&Vt[(row << 5) + voff];
                mma_tf32(o[nt], a0, a1, a2, a3,
                         __float_as_uint(vb.x), __float_as_uint(vb.y));
            }
        }
    }

    // ---- epilogue: normalize, tf32-round, write g_o [B,S,D] ----
    const int b = bh >> 4, h = bh & 15;
    const float inv0 = 1.f / l0, inv1 = 1.f / l1;
    const int row0 = qbase + wrow + g;
    const int row1 = row0 + 8;
    float* O0 = g_o + ((size_t)(b * Ss + row0)) * Dd + (h << 6);
    float* O1 = g_o + ((size_t)(b * Ss + row1)) * Dd + (h << 6);
#pragma unroll
    for (int nt = 0; nt < 8; ++nt) {
        const int cl = (nt << 3) + (c << 1);
        O0[cl]     = rndtf(o[nt][0] * inv0);
        O0[cl + 1] = rndtf(o[nt][1] * inv0);
        O1[cl]     = rndtf(o[nt][2] * inv1);
        O1[cl + 1] = rndtf(o[nt][3] * inv1);
    }
#undef PREFETCH_KV
}

// ---------------------------------------------------------------------------
// Launch. Inputs: 0 query, 1 key, 2 value, 3 mask (tril; hardcoded),
// 4..11: wq_w, wq_b, wk_w, wk_b, wv_w, wv_b, wo_w, wo_b.
// ---------------------------------------------------------------------------
extern "C" void kernel_launch(void* const* d_in, const int* in_sizes, int n_in,
                              void* d_out, int out_size)
{
    const float* query = (const float*)d_in[0];
    const float* key   = (const float*)d_in[1];
    const float* value = (const float*)d_in[2];
    const float* wq_w  = (const float*)d_in[4];
    const float* wq_b  = (const float*)d_in[5];
    const float* wk_w  = (const float*)d_in[6];
    const float* wk_b  = (const float*)d_in[7];
    const float* wv_w  = (const float*)d_in[8];
    const float* wv_b  = (const float*)d_in[9];
    const float* wo_w  = (const float*)d_in[10];
    const float* wo_b  = (const float*)d_in[11];
    float* out = (float*)d_out;

    const dim3 pi_grid((Bb * Ss * Dd) / 4 / 256, 1, 3);
    const dim3 pw_grid((Dd * Dd) / 4 / 256, 1, 4);
    const dim3 qkv_grid(Dd / 128, (Bb * Ss) / 128, 3);
    const dim3 gemm_grid(Dd / 128, (Bb * Ss) / 128);
    const dim3 attn_grid(Ss / 128, Bb * Hh);  // (16, 32)

    preround_inp<<<pi_grid, 256>>>(query, key, value);
    preround_w<<<pw_grid, 256>>>(wq_w, wk_w, wv_w, wo_w);
    qkv_gemm<<<qkv_grid, 128>>>(wq_b, wk_b, wv_b);
    flash_attn_mma<<<attn_grid, 256>>>();
    out_gemm<<<gemm_grid, 128>>>(wo_b, out);
}